// round 1
// baseline (speedup 1.0000x reference)
#include <cuda_runtime.h>
#include <cuda_fp16.h>
#include <cstdint>

// Problem constants
#define GRID_HW 512
#define BATCH 4
#define NFEAT 16
#define NPOINTS (BATCH * GRID_HW * GRID_HW)   // 1,048,576
#define OUT_PLANE (GRID_HW * GRID_HW)         // 262,144

// Transposed fp16 texture scratch: layout (H, W, F) per mip, F innermost.
// Sizes (halves): 1024^2*16 + 512^2*16 + 256^2*16 + 128^2*16 = 22,282,240
#define SCRATCH_HALVES 22282240
__device__ __align__(16) __half g_tex[SCRATCH_HALVES];

// ---------------------------------------------------------------------------
// Kernel 1: transpose one mip level (F,H,W) fp32 -> (H,W,F) fp16
// One thread per texel (y,x); reads 16 strided floats (coalesced across
// threads per feature plane), writes 32 contiguous bytes (2x uint4).
// ---------------------------------------------------------------------------
__global__ void transpose_kernel(const float* __restrict__ src, int HW,
                                 int dstOffHalves) {
    int i = blockIdx.x * blockDim.x + threadIdx.x;
    if (i >= HW) return;
    __half2 h[8];
#pragma unroll
    for (int f = 0; f < 8; f++) {
        float a = src[(2 * f) * HW + i];
        float b = src[(2 * f + 1) * HW + i];
        h[f] = __floats2half2_rn(a, b);
    }
    uint4* dst = reinterpret_cast<uint4*>(g_tex + dstOffHalves + (size_t)i * NFEAT);
    dst[0] = *reinterpret_cast<const uint4*>(&h[0]);
    dst[1] = *reinterpret_cast<const uint4*>(&h[4]);
}

// ---------------------------------------------------------------------------
// Kernel 2: bilinear grid-sample (border clamp, align_corners=False) over 4
// mips, summed. One thread per output point (b, ho, wo); 16-feature fp32
// accumulator; each tap = one 32B sector (2x LDG.128).
// ---------------------------------------------------------------------------
__device__ __forceinline__ void accum_tap(float2* acc, uint4 a, uint4 b, float w) {
    const __half2* ha = reinterpret_cast<const __half2*>(&a);
    const __half2* hb = reinterpret_cast<const __half2*>(&b);
#pragma unroll
    for (int j = 0; j < 4; j++) {
        float2 v = __half22float2(ha[j]);
        acc[j].x = fmaf(w, v.x, acc[j].x);
        acc[j].y = fmaf(w, v.y, acc[j].y);
    }
#pragma unroll
    for (int j = 0; j < 4; j++) {
        float2 v = __half22float2(hb[j]);
        acc[4 + j].x = fmaf(w, v.x, acc[4 + j].x);
        acc[4 + j].y = fmaf(w, v.y, acc[4 + j].y);
    }
}

__global__ __launch_bounds__(256) void sample_kernel(
    const float2* __restrict__ grid, float* __restrict__ out) {
    int tid = blockIdx.x * blockDim.x + threadIdx.x;
    if (tid >= NPOINTS) return;

    float2 g = grid[tid];

    float2 acc[8];
#pragma unroll
    for (int j = 0; j < 8; j++) acc[j] = make_float2(0.f, 0.f);

    // mip sizes and offsets in uint4 units (16 halves per texel = 2 uint4)
    const int Ws[4]     = {1024, 512, 256, 128};
    const int offU4[4]  = {0, 2097152, 2621440, 2752512};

    const uint4* gt = reinterpret_cast<const uint4*>(g_tex);

#pragma unroll
    for (int m = 0; m < 4; m++) {
        const int   W  = Ws[m];
        const float fW = (float)W;
        // unnormalize + border clip (matches reference formula exactly, fp32)
        float ix = fminf(fmaxf(((g.x + 1.0f) * fW - 1.0f) * 0.5f, 0.0f), fW - 1.0f);
        float iy = fminf(fmaxf(((g.y + 1.0f) * fW - 1.0f) * 0.5f, 0.0f), fW - 1.0f);
        float x0f = floorf(ix), y0f = floorf(iy);
        float wx = ix - x0f,    wy = iy - y0f;
        int x0 = (int)x0f, y0 = (int)y0f;
        int x1 = min(x0 + 1, W - 1);
        int y1 = min(y0 + 1, W - 1);

        const uint4* base = gt + offU4[m];
        const uint4* p00 = base + (size_t)(y0 * W + x0) * 2;
        const uint4* p01 = base + (size_t)(y0 * W + x1) * 2;
        const uint4* p10 = base + (size_t)(y1 * W + x0) * 2;
        const uint4* p11 = base + (size_t)(y1 * W + x1) * 2;

        // Issue all 8 loads up-front for MLP before any converts
        uint4 a00 = p00[0], b00 = p00[1];
        uint4 a01 = p01[0], b01 = p01[1];
        uint4 a10 = p10[0], b10 = p10[1];
        uint4 a11 = p11[0], b11 = p11[1];

        float w00 = (1.0f - wx) * (1.0f - wy);
        float w01 = wx * (1.0f - wy);
        float w10 = (1.0f - wx) * wy;
        float w11 = wx * wy;

        accum_tap(acc, a00, b00, w00);
        accum_tap(acc, a01, b01, w01);
        accum_tap(acc, a10, b10, w10);
        accum_tap(acc, a11, b11, w11);
    }

    // Output layout (B, F, Ho, Wo); adjacent threads (wo) -> coalesced per plane
    int wo = tid & (GRID_HW - 1);
    int ho = (tid >> 9) & (GRID_HW - 1);
    int b  = tid >> 18;
    float* o = out + ((size_t)b * NFEAT) * OUT_PLANE + (size_t)ho * GRID_HW + wo;
#pragma unroll
    for (int f = 0; f < 8; f++) {
        o[(size_t)(2 * f)     * OUT_PLANE] = acc[f].x;
        o[(size_t)(2 * f + 1) * OUT_PLANE] = acc[f].y;
    }
}

// ---------------------------------------------------------------------------
extern "C" void kernel_launch(void* const* d_in, const int* in_sizes, int n_in,
                              void* d_out, int out_size) {
    const float* x    = (const float*)d_in[0];  // (B, 512, 512, 2)
    const float* tex1 = (const float*)d_in[1];  // (16, 1024, 1024)
    const float* tex2 = (const float*)d_in[2];  // (16, 512, 512)
    const float* tex3 = (const float*)d_in[3];  // (16, 256, 256)
    const float* tex4 = (const float*)d_in[4];  // (16, 128, 128)
    float* out = (float*)d_out;

    // Transpose all 4 mips into fp16 (H,W,F) scratch
    {
        const int HW1 = 1024 * 1024, HW2 = 512 * 512, HW3 = 256 * 256, HW4 = 128 * 128;
        transpose_kernel<<<(HW1 + 255) / 256, 256>>>(tex1, HW1, 0);
        transpose_kernel<<<(HW2 + 255) / 256, 256>>>(tex2, HW2, 16777216);
        transpose_kernel<<<(HW3 + 255) / 256, 256>>>(tex3, HW3, 20971520);
        transpose_kernel<<<(HW4 + 255) / 256, 256>>>(tex4, HW4, 22020096);
    }

    // Sample
    sample_kernel<<<(NPOINTS + 255) / 256, 256>>>(
        reinterpret_cast<const float2*>(x), out);
}

// round 4
// speedup vs baseline: 1.6963x; 1.6963x over previous
#include <cuda_runtime.h>
#include <cuda_fp16.h>
#include <cstdint>

// Problem constants
#define GRID_HW 512
#define BATCH 4
#define NFEAT 16
#define NPOINTS (BATCH * GRID_HW * GRID_HW)   // 1,048,576
#define OUT_PLANE (GRID_HW * GRID_HW)         // 262,144

// Transposed fp16 texture scratch: layout (H, W, F) per mip, F innermost.
// Sizes (halves): 1024^2*16 + 512^2*16 + 256^2*16 + 128^2*16 = 22,282,240
#define SCRATCH_HALVES 22282240
__device__ __align__(16) __half g_tex[SCRATCH_HALVES];

// ---------------------------------------------------------------------------
// Kernel 1: transpose ALL mips (F,H,W) fp32 -> (H,W,F) fp16, one launch.
// Block ranges: [0,4096) mip1, [4096,5120) mip2, [5120,5376) mip3,
// [5376,5440) mip4. One thread per texel.
// ---------------------------------------------------------------------------
__global__ __launch_bounds__(256) void transpose_all(
    const float* __restrict__ t1, const float* __restrict__ t2,
    const float* __restrict__ t3, const float* __restrict__ t4) {
    int blk = blockIdx.x;
    const float* src;
    int HW, offH, i;
    if (blk < 4096)      { src = t1; HW = 1 << 20; offH = 0;        i = blk * 256; }
    else if (blk < 5120) { src = t2; HW = 1 << 18; offH = 16777216; i = (blk - 4096) * 256; }
    else if (blk < 5376) { src = t3; HW = 1 << 16; offH = 20971520; i = (blk - 5120) * 256; }
    else                 { src = t4; HW = 1 << 14; offH = 22020096; i = (blk - 5376) * 256; }
    i += threadIdx.x;

    __half2 h[8];
#pragma unroll
    for (int f = 0; f < 8; f++) {
        float a = src[(size_t)(2 * f) * HW + i];
        float b = src[(size_t)(2 * f + 1) * HW + i];
        h[f] = __floats2half2_rn(a, b);
    }
    uint4* dst = reinterpret_cast<uint4*>(g_tex + offH + (size_t)i * NFEAT);
    dst[0] = *reinterpret_cast<const uint4*>(&h[0]);
    dst[1] = *reinterpret_cast<const uint4*>(&h[4]);
}

// ---------------------------------------------------------------------------
// Kernel 2: bilinear grid-sample (border, align_corners=False) over 4 mips.
// FOUR lanes per point: sub = lane&3, featHalf = sub&1 (which 8 features),
// tap = sub>>1 (x0 or x1). Each lane: 2 loads per mip (rows y0,y1), 16B each.
// Lane pairs (featHalf 0/1) cover one 32B texel; x-tap pairs are adjacent
// texels -> one warp LDG.128 instruction touches ~1.25 cache lines per point
// instead of 4. Cross-tap sum via shfl_xor(2).
// ---------------------------------------------------------------------------
__global__ __launch_bounds__(256) void sample_kernel(
    const float2* __restrict__ grid, float* __restrict__ out) {
    int t = blockIdx.x * 256 + threadIdx.x;      // 4M threads
    int p        = t >> 2;                        // point id
    int sub      = t & 3;
    int featHalf = sub & 1;
    int tap      = sub >> 1;

    float2 g = grid[p];

    const int Ws[4]    = {1024, 512, 256, 128};
    const int offU4[4] = {0, 2097152, 2621440, 2752512};
    const uint4* gt = reinterpret_cast<const uint4*>(g_tex);

    uint4 ld[8];
    float w0[4], w1[4];

#pragma unroll
    for (int m = 0; m < 4; m++) {
        const int   W  = Ws[m];
        const float fW = (float)W;
        float ix = fminf(fmaxf(((g.x + 1.0f) * fW - 1.0f) * 0.5f, 0.0f), fW - 1.0f);
        float iy = fminf(fmaxf(((g.y + 1.0f) * fW - 1.0f) * 0.5f, 0.0f), fW - 1.0f);
        float x0f = floorf(ix), y0f = floorf(iy);
        float wx = ix - x0f, wy = iy - y0f;
        int x0 = (int)x0f, y0 = (int)y0f;
        int y1 = min(y0 + 1, W - 1);
        int xt = min(x0 + tap, W - 1);          // this lane's x tap
        float wxt = tap ? wx : (1.0f - wx);
        w0[m] = wxt * (1.0f - wy);
        w1[m] = wxt * wy;

        const uint4* base = gt + offU4[m];
        ld[2 * m]     = base[(size_t)(y0 * W + xt) * 2 + featHalf];
        ld[2 * m + 1] = base[(size_t)(y1 * W + xt) * 2 + featHalf];
    }

    // Accumulate 8 features (4 half2) in fp32
    float2 acc[4];
#pragma unroll
    for (int j = 0; j < 4; j++) acc[j] = make_float2(0.f, 0.f);
#pragma unroll
    for (int m = 0; m < 4; m++) {
        const __half2* h0 = reinterpret_cast<const __half2*>(&ld[2 * m]);
        const __half2* h1 = reinterpret_cast<const __half2*>(&ld[2 * m + 1]);
#pragma unroll
        for (int j = 0; j < 4; j++) {
            float2 v0 = __half22float2(h0[j]);
            float2 v1 = __half22float2(h1[j]);
            acc[j].x = fmaf(w0[m], v0.x, fmaf(w1[m], v1.x, acc[j].x));
            acc[j].y = fmaf(w0[m], v0.y, fmaf(w1[m], v1.y, acc[j].y));
        }
    }

    // Sum the two x-taps: partner lane = lane ^ 2 (same point, same featHalf)
#pragma unroll
    for (int j = 0; j < 4; j++) {
        acc[j].x += __shfl_xor_sync(0xFFFFFFFFu, acc[j].x, 2);
        acc[j].y += __shfl_xor_sync(0xFFFFFFFFu, acc[j].y, 2);
    }

    // Each lane writes 4 features: f0 = featHalf*8 + tap*4 (all lanes active).
    // Per STG instruction: 8 consecutive points x 4 planes -> ~4 wavefronts.
    int wo = p & (GRID_HW - 1);
    int ho = (p >> 9) & (GRID_HW - 1);
    int b  = p >> 18;
    int f0 = featHalf * 8 + tap * 4;
    int jb = tap * 2;   // acc[jb], acc[jb+1] hold feats f0..f0+3 of this half
    float* o = out + ((size_t)b * NFEAT + f0) * OUT_PLANE
                   + (size_t)ho * GRID_HW + wo;
    o[0]                     = acc[jb].x;
    o[OUT_PLANE]             = acc[jb].y;
    o[(size_t)2 * OUT_PLANE] = acc[jb + 1].x;
    o[(size_t)3 * OUT_PLANE] = acc[jb + 1].y;
}

// ---------------------------------------------------------------------------
extern "C" void kernel_launch(void* const* d_in, const int* in_sizes, int n_in,
                              void* d_out, int out_size) {
    const float* x    = (const float*)d_in[0];  // (B, 512, 512, 2)
    const float* tex1 = (const float*)d_in[1];  // (16, 1024, 1024)
    const float* tex2 = (const float*)d_in[2];  // (16, 512, 512)
    const float* tex3 = (const float*)d_in[3];  // (16, 256, 256)
    const float* tex4 = (const float*)d_in[4];  // (16, 128, 128)
    float* out = (float*)d_out;

    transpose_all<<<5440, 256>>>(tex1, tex2, tex3, tex4);

    // 4 lanes per point -> 4M threads
    sample_kernel<<<(NPOINTS * 4) / 256, 256>>>(
        reinterpret_cast<const float2*>(x), out);
}

// round 13
// speedup vs baseline: 1.7190x; 1.0134x over previous
#include <cuda_runtime.h>
#include <cuda_fp16.h>
#include <cstdint>

// Problem constants
#define GRID_HW 512
#define BATCH 4
#define NFEAT 16
#define NPOINTS (BATCH * GRID_HW * GRID_HW)   // 1,048,576
#define OUT_PLANE (GRID_HW * GRID_HW)         // 262,144

// Transposed fp16 texture scratch: layout (H, W, F) per mip, F innermost.
// Sizes (halves): 1024^2*16 + 512^2*16 + 256^2*16 + 128^2*16 = 22,282,240
#define SCRATCH_HALVES 22282240
__device__ __align__(16) __half g_tex[SCRATCH_HALVES];

// ---------------------------------------------------------------------------
// Kernel 1: transpose ALL mips (F,H,W) fp32 -> (H,W,F) fp16, one launch.
// Block ranges: [0,4096) mip1, [4096,5120) mip2, [5120,5376) mip3,
// [5376,5440) mip4. One thread per texel.
// ---------------------------------------------------------------------------
__global__ __launch_bounds__(256) void transpose_all(
    const float* __restrict__ t1, const float* __restrict__ t2,
    const float* __restrict__ t3, const float* __restrict__ t4) {
    int blk = blockIdx.x;
    const float* src;
    int HW, offH, i;
    if (blk < 4096)      { src = t1; HW = 1 << 20; offH = 0;        i = blk * 256; }
    else if (blk < 5120) { src = t2; HW = 1 << 18; offH = 16777216; i = (blk - 4096) * 256; }
    else if (blk < 5376) { src = t3; HW = 1 << 16; offH = 20971520; i = (blk - 5120) * 256; }
    else                 { src = t4; HW = 1 << 14; offH = 22020096; i = (blk - 5376) * 256; }
    i += threadIdx.x;

    __half2 h[8];
#pragma unroll
    for (int f = 0; f < 8; f++) {
        float a = src[(size_t)(2 * f) * HW + i];
        float b = src[(size_t)(2 * f + 1) * HW + i];
        h[f] = __floats2half2_rn(a, b);
    }
    uint4* dst = reinterpret_cast<uint4*>(g_tex + offH + (size_t)i * NFEAT);
    dst[0] = *reinterpret_cast<const uint4*>(&h[0]);
    dst[1] = *reinterpret_cast<const uint4*>(&h[4]);
}

// ---------------------------------------------------------------------------
// Kernel 2: bilinear grid-sample (border, align_corners=False) over 4 mips.
// FOUR lanes per point: sub = lane&3, featHalf = sub&1 (which 8 features),
// tap = sub>>1 (x0 or x1). Each lane: 2 loads per mip (rows y0,y1), 16B each.
// Lane pairs (featHalf 0/1) cover one 32B texel; x-tap pairs are adjacent
// texels -> one warp LDG.128 instruction touches ~1.25 cache lines per point
// instead of 4. Cross-tap sum via shfl_xor(2).
// __launch_bounds__(256, 8): pin regs <=32 for 8 CTAs/SM (100% occupancy).
// ---------------------------------------------------------------------------
__global__ __launch_bounds__(256, 8) void sample_kernel(
    const float2* __restrict__ grid, float* __restrict__ out) {
    int t = blockIdx.x * 256 + threadIdx.x;      // 4M threads
    int p        = t >> 2;                        // point id
    int sub      = t & 3;
    int featHalf = sub & 1;
    int tap      = sub >> 1;

    float2 g = grid[p];

    const int Ws[4]    = {1024, 512, 256, 128};
    const int offU4[4] = {0, 2097152, 2621440, 2752512};
    const uint4* gt = reinterpret_cast<const uint4*>(g_tex);

    // wxt = tap ? wx : (1-wx)  ==  base + sgn*wx  (one FMA, no select chain)
    const float wbase = tap ? 0.0f : 1.0f;
    const float wsgn  = tap ? 1.0f : -1.0f;

    uint4 ld[8];
    float w0[4], w1[4];

#pragma unroll
    for (int m = 0; m < 4; m++) {
        const int   W  = Ws[m];
        const float fW = (float)W;
        float ix = fminf(fmaxf(((g.x + 1.0f) * fW - 1.0f) * 0.5f, 0.0f), fW - 1.0f);
        float iy = fminf(fmaxf(((g.y + 1.0f) * fW - 1.0f) * 0.5f, 0.0f), fW - 1.0f);
        float x0f = floorf(ix), y0f = floorf(iy);
        float wx = ix - x0f, wy = iy - y0f;
        int x0 = (int)x0f, y0 = (int)y0f;
        int y1 = min(y0 + 1, W - 1);
        int xt = min(x0 + tap, W - 1);          // this lane's x tap
        float wxt = fmaf(wsgn, wx, wbase);
        w0[m] = wxt * (1.0f - wy);
        w1[m] = wxt * wy;

        const uint4* bp = gt + offU4[m];
        ld[2 * m]     = bp[(size_t)(y0 * W + xt) * 2 + featHalf];
        ld[2 * m + 1] = bp[(size_t)(y1 * W + xt) * 2 + featHalf];
    }

    // Accumulate 8 features (4 half2) in fp32
    float2 acc[4];
#pragma unroll
    for (int j = 0; j < 4; j++) acc[j] = make_float2(0.f, 0.f);
#pragma unroll
    for (int m = 0; m < 4; m++) {
        const __half2* h0 = reinterpret_cast<const __half2*>(&ld[2 * m]);
        const __half2* h1 = reinterpret_cast<const __half2*>(&ld[2 * m + 1]);
#pragma unroll
        for (int j = 0; j < 4; j++) {
            float2 v0 = __half22float2(h0[j]);
            float2 v1 = __half22float2(h1[j]);
            acc[j].x = fmaf(w0[m], v0.x, fmaf(w1[m], v1.x, acc[j].x));
            acc[j].y = fmaf(w0[m], v0.y, fmaf(w1[m], v1.y, acc[j].y));
        }
    }

    // Sum the two x-taps: partner lane = lane ^ 2 (same point, same featHalf)
#pragma unroll
    for (int j = 0; j < 4; j++) {
        acc[j].x += __shfl_xor_sync(0xFFFFFFFFu, acc[j].x, 2);
        acc[j].y += __shfl_xor_sync(0xFFFFFFFFu, acc[j].y, 2);
    }

    // Each lane writes 4 features: f0 = featHalf*8 + tap*4 (all lanes active).
    int wo = p & (GRID_HW - 1);
    int ho = (p >> 9) & (GRID_HW - 1);
    int b  = p >> 18;
    int f0 = featHalf * 8 + tap * 4;
    int jb = tap * 2;   // acc[jb], acc[jb+1] hold feats f0..f0+3 of this half
    float* o = out + ((size_t)b * NFEAT + f0) * OUT_PLANE
                   + (size_t)ho * GRID_HW + wo;
    o[0]                     = acc[jb].x;
    o[OUT_PLANE]             = acc[jb].y;
    o[(size_t)2 * OUT_PLANE] = acc[jb + 1].x;
    o[(size_t)3 * OUT_PLANE] = acc[jb + 1].y;
}

// ---------------------------------------------------------------------------
extern "C" void kernel_launch(void* const* d_in, const int* in_sizes, int n_in,
                              void* d_out, int out_size) {
    const float* x    = (const float*)d_in[0];  // (B, 512, 512, 2)
    const float* tex1 = (const float*)d_in[1];  // (16, 1024, 1024)
    const float* tex2 = (const float*)d_in[2];  // (16, 512, 512)
    const float* tex3 = (const float*)d_in[3];  // (16, 256, 256)
    const float* tex4 = (const float*)d_in[4];  // (16, 128, 128)
    float* out = (float*)d_out;

    transpose_all<<<5440, 256>>>(tex1, tex2, tex3, tex4);

    // 4 lanes per point -> 4M threads
    sample_kernel<<<(NPOINTS * 4) / 256, 256>>>(
        reinterpret_cast<const float2*>(x), out);
}